// round 3
// baseline (speedup 1.0000x reference)
#include <cuda_runtime.h>
#include <cstdint>

#define S_LEN 1024
#define CS 768
#define CZ 128
#define NH 24
#define HD 32
#define NB 2
#define NROWS (NB * S_LEN)      // 2048
#define EPS 1e-5f
#define NEG_INF (-1e9f)

// ---------------- f32x2 helpers ----------------
#define FMA2(c, a, b) asm("fma.rn.f32x2 %0, %1, %2, %0;" : "+l"(c) : "l"(a), "l"(b))
#define MUL2(c, a)    asm("mul.rn.f32x2 %0, %0, %1;" : "+l"(c) : "l"(a))

__device__ __forceinline__ unsigned long long pack_dup(float x) {
    unsigned long long r;
    asm("mov.b64 %0, {%1, %1};" : "=l"(r) : "r"(__float_as_uint(x)));
    return r;
}
__device__ __forceinline__ unsigned long long add2(unsigned long long a, unsigned long long b) {
    unsigned long long r;
    asm("add.rn.f32x2 %0, %1, %2;" : "=l"(r) : "l"(a), "l"(b));
    return r;
}
__device__ __forceinline__ float2 unpack2(unsigned long long v) {
    unsigned lo, hi;
    asm("mov.b64 {%0, %1}, %2;" : "=r"(lo), "=r"(hi) : "l"(v));
    return make_float2(__uint_as_float(lo), __uint_as_float(hi));
}

// ---------------- scratch ----------------
__device__ float g_emb[NB * 3 * CS];
__device__ float g_bsn[NROWS * CS];
__device__ float g_q[NROWS * CS];
__device__ float g_k[NROWS * CS];
__device__ float g_v[NROWS * CS];
__device__ float g_ao[NROWS * CS];
__device__ float g_bias[(size_t)NH * S_LEN * S_LEN];
__device__ float g_wz2[CZ * NH];
__device__ float g_wsum[NH];
__device__ float g_bias0[NH];

// ---------------- setup: fold ln_z into w_z ----------------
__global__ void setup_wz_kernel(const float* __restrict__ lnw,
                                const float* __restrict__ lnb,
                                const float* __restrict__ wz) {
    int tid = threadIdx.x;  // 128
    for (int idx = tid; idx < CZ * NH; idx += 128) {
        int c = idx / NH;
        g_wz2[idx] = lnw[c] * wz[idx];
    }
    __syncthreads();
    if (tid < NH) {
        float s = 0.f, b0 = 0.f;
        for (int c = 0; c < CZ; c++) {
            s += g_wz2[c * NH + tid];
            b0 += lnb[c] * wz[c * NH + tid];
        }
        g_wsum[tid] = s;
        g_bias0[tid] = b0;
    }
}

// ---------------- adaLN embedding, parallel over columns ----------------
// grid (18, NB), 128 threads: col = bx*128+tid over 2304 outputs
__global__ void emb_kernel(const float* __restrict__ t,
                           const float* __restrict__ w,
                           const float* __restrict__ ba) {
    __shared__ float st[CS];
    int b = blockIdx.y;
    int tid = threadIdx.x;
    int col = blockIdx.x * 128 + tid;
    for (int kk = tid; kk < CS; kk += 128) {
        float x = t[b * CS + kk];
        st[kk] = x / (1.f + __expf(-x));
    }
    __syncthreads();
    float acc = ba[col];
#pragma unroll 8
    for (int k = 0; k < CS; k++)
        acc = fmaf(st[k], w[(size_t)k * (3 * CS) + col], acc);
    g_emb[b * 3 * CS + col] = acc;
}

// ---------------- bs LayerNorm + adaLN modulate ----------------
__global__ void bsnorm_kernel(const float* __restrict__ bs) {
    int r = blockIdx.x;
    int tid = threadIdx.x;  // 256
    int b = r >> 10;
    const float* x = bs + (size_t)r * CS;
    float v[3];
    float s = 0.f, s2 = 0.f;
#pragma unroll
    for (int k = 0; k < 3; k++) {
        v[k] = x[tid + k * 256];
        s += v[k];
        s2 = fmaf(v[k], v[k], s2);
    }
#pragma unroll
    for (int o = 16; o > 0; o >>= 1) {
        s += __shfl_xor_sync(0xffffffffu, s, o);
        s2 += __shfl_xor_sync(0xffffffffu, s2, o);
    }
    __shared__ float rs[8], rs2[8];
    int wid = tid >> 5, lane = tid & 31;
    if (lane == 0) { rs[wid] = s; rs2[wid] = s2; }
    __syncthreads();
    float S = 0.f, S2 = 0.f;
#pragma unroll
    for (int w = 0; w < 8; w++) { S += rs[w]; S2 += rs2[w]; }
    float mu = S * (1.f / CS);
    float var = S2 * (1.f / CS) - mu * mu;
    float rstd = rsqrtf(var + EPS);
    const float* eb = g_emb + b * 3 * CS;
#pragma unroll
    for (int k = 0; k < 3; k++) {
        int c = tid + k * 256;
        g_bsn[(size_t)r * CS + c] = (v[k] - mu) * rstd * (1.f + eb[CS + c]) + eb[c];
    }
}

// ---------------- 128x64-tile fp32 GEMM with packed f32x2 FMA ----------------
// blockIdx.z selects (W,C) triple; epi=1 applies (x+bo)*gate epilogue.
__global__ __launch_bounds__(128, 2) void gemm_kernel2(
    const float* __restrict__ A,
    const float* __restrict__ Wa, const float* __restrict__ Wb, const float* __restrict__ Wc,
    float* __restrict__ Ca, float* __restrict__ Cb, float* __restrict__ Cc,
    const float* __restrict__ bo, int epi) {
    __shared__ __align__(16) float As[2][16][132];   // [k][row], padded for LDS.64 align + banks
    __shared__ __align__(16) float2 Bs[2][16][64];   // duplicated {b,b} pairs

    int tid = threadIdx.x;
    int z = blockIdx.z;
    const float* W = (z == 0) ? Wa : (z == 1) ? Wb : Wc;
    float* C = (z == 0) ? Ca : (z == 1) ? Cb : Cc;

    int row0 = blockIdx.y * 128;
    int col0 = blockIdx.x * 64;
    int tx = tid & 7, ty = tid >> 3;
    int r0 = ty * 8, c0 = tx * 8;

    int ar = tid >> 2, aq = (tid & 3) * 4;   // A loads: rows ar+32i, k-quad aq
    int bk = tid >> 4, bq = (tid & 15) * 4;  // B loads: k rows bk+8i, col-quad bq

    unsigned long long acc[4][8];
#pragma unroll
    for (int p = 0; p < 4; p++)
#pragma unroll
        for (int j = 0; j < 8; j++) acc[p][j] = 0ULL;

    float4 ra[4], rb[2];
#pragma unroll
    for (int i = 0; i < 4; i++)
        ra[i] = *(const float4*)&A[(size_t)(row0 + ar + i * 32) * CS + aq];
#pragma unroll
    for (int i = 0; i < 2; i++)
        rb[i] = *(const float4*)&W[(size_t)(bk + i * 8) * CS + col0 + bq];

    int buf = 0;
    for (int kt = 0; kt < 48; kt++) {
#pragma unroll
        for (int i = 0; i < 4; i++) {
            int rr = ar + i * 32;
            As[buf][aq + 0][rr] = ra[i].x;
            As[buf][aq + 1][rr] = ra[i].y;
            As[buf][aq + 2][rr] = ra[i].z;
            As[buf][aq + 3][rr] = ra[i].w;
        }
#pragma unroll
        for (int i = 0; i < 2; i++) {
            int kk = bk + i * 8;
            Bs[buf][kk][bq + 0] = make_float2(rb[i].x, rb[i].x);
            Bs[buf][kk][bq + 1] = make_float2(rb[i].y, rb[i].y);
            Bs[buf][kk][bq + 2] = make_float2(rb[i].z, rb[i].z);
            Bs[buf][kk][bq + 3] = make_float2(rb[i].w, rb[i].w);
        }
        __syncthreads();
        if (kt < 47) {
            int k0 = (kt + 1) * 16;
#pragma unroll
            for (int i = 0; i < 4; i++)
                ra[i] = *(const float4*)&A[(size_t)(row0 + ar + i * 32) * CS + k0 + aq];
#pragma unroll
            for (int i = 0; i < 2; i++)
                rb[i] = *(const float4*)&W[(size_t)(k0 + bk + i * 8) * CS + col0 + bq];
        }
#pragma unroll
        for (int k = 0; k < 16; k++) {
            unsigned long long a2[4], b2[8];
#pragma unroll
            for (int p = 0; p < 4; p++)
                a2[p] = *(const unsigned long long*)&As[buf][k][r0 + 2 * p];
#pragma unroll
            for (int j = 0; j < 8; j++)
                b2[j] = *(const unsigned long long*)&Bs[buf][k][c0 + j];
#pragma unroll
            for (int p = 0; p < 4; p++)
#pragma unroll
                for (int j = 0; j < 8; j++) FMA2(acc[p][j], a2[p], b2[j]);
        }
        buf ^= 1;
    }

#pragma unroll
    for (int p = 0; p < 4; p++) {
        float lo[8], hi[8];
#pragma unroll
        for (int j = 0; j < 8; j++) {
            float2 u = unpack2(acc[p][j]);
            lo[j] = u.x;
            hi[j] = u.y;
        }
        int rlo = row0 + r0 + 2 * p;
        int col = col0 + c0;
        if (epi) {
            const float* eb = g_emb + (rlo >> 10) * 3 * CS + 2 * CS + col;
#pragma unroll
            for (int j = 0; j < 8; j++) {
                float bj = bo[col + j], gj = eb[j];
                lo[j] = (lo[j] + bj) * gj;
                hi[j] = (hi[j] + bj) * gj;
            }
        }
        *(float4*)&C[(size_t)rlo * CS + col] = make_float4(lo[0], lo[1], lo[2], lo[3]);
        *(float4*)&C[(size_t)rlo * CS + col + 4] = make_float4(lo[4], lo[5], lo[6], lo[7]);
        *(float4*)&C[(size_t)(rlo + 1) * CS + col] = make_float4(hi[0], hi[1], hi[2], hi[3]);
        *(float4*)&C[(size_t)(rlo + 1) * CS + col + 4] = make_float4(hi[4], hi[5], hi[6], hi[7]);
    }
}

// ---------------- RMS norm over D=32 groups ----------------
__global__ void rms_kernel(const float* __restrict__ w, int which) {
    int g = blockIdx.x * blockDim.x + threadIdx.x;
    if (g >= NROWS * NH) return;
    float* p = ((which == 0) ? g_q : g_k) + (size_t)g * HD;
    float4 v[8];
    float ss = 0.f;
#pragma unroll
    for (int e = 0; e < 8; e++) {
        v[e] = ((float4*)p)[e];
        ss = fmaf(v[e].x, v[e].x, ss);
        ss = fmaf(v[e].y, v[e].y, ss);
        ss = fmaf(v[e].z, v[e].z, ss);
        ss = fmaf(v[e].w, v[e].w, ss);
    }
    float r = rsqrtf(ss * (1.f / HD) + EPS);
#pragma unroll
    for (int e = 0; e < 8; e++) {
        v[e].x *= r * w[e * 4 + 0];
        v[e].y *= r * w[e * 4 + 1];
        v[e].z *= r * w[e * 4 + 2];
        v[e].w *= r * w[e * 4 + 3];
        ((float4*)p)[e] = v[e];
    }
}

// ---------------- z bias: LN(z) @ wz + mask (f32x2) ----------------
__global__ __launch_bounds__(256) void bias_kernel(const float* __restrict__ z,
                                                   const int* __restrict__ zmask) {
    __shared__ float swz[CZ * NH];
    __shared__ float swsum[NH], sbias0[NH];
    int tid = threadIdx.x;
    for (int idx = tid; idx < CZ * NH; idx += 256) swz[idx] = g_wz2[idx];
    if (tid < NH) { swsum[tid] = g_wsum[tid]; sbias0[tid] = g_bias0[tid]; }
    __syncthreads();

    int p = blockIdx.x * 256 + tid;
    int i = p >> 10, j = p & 1023;
    int msk = zmask[p];

    unsigned long long acc[12];
#pragma unroll
    for (int q = 0; q < 12; q++) acc[q] = 0ULL;
    float s = 0.f, s2 = 0.f;

    if (msk) {
        const float4* zp = (const float4*)(z + ((size_t)p << 7));
#pragma unroll 2
        for (int c4 = 0; c4 < 32; c4++) {
            float4 zv = __ldg(&zp[c4]);
            float ze[4] = {zv.x, zv.y, zv.z, zv.w};
#pragma unroll
            for (int e = 0; e < 4; e++) {
                float zc = ze[e];
                s += zc;
                s2 = fmaf(zc, zc, s2);
                unsigned long long zz = pack_dup(zc);
                const unsigned long long* wp =
                    (const unsigned long long*)(swz + (c4 * 4 + e) * NH);
#pragma unroll
                for (int q = 0; q < 12; q++) FMA2(acc[q], zz, wp[q]);
            }
        }
    }
    float mu = s * (1.f / CZ);
    float var = s2 * (1.f / CZ) - mu * mu;
    float rinv = rsqrtf(var + EPS);
    float* ob = g_bias + ((size_t)i << 10) + j;
#pragma unroll
    for (int q = 0; q < 12; q++) {
        float2 u = unpack2(acc[q]);
        int h0 = 2 * q, h1 = 2 * q + 1;
        float v0 = rinv * (u.x - mu * swsum[h0]) + sbias0[h0];
        float v1 = rinv * (u.y - mu * swsum[h1]) + sbias0[h1];
        ob[(size_t)h0 << 20] = msk ? v0 : NEG_INF;
        ob[(size_t)h1 << 20] = msk ? v1 : NEG_INF;
    }
}

// ---------------- flash attention, packed f32x2 ----------------
__global__ __launch_bounds__(128, 3) void attn_kernel(const float* __restrict__ beta) {
    __shared__ __align__(16) float kts[32][34];  // transposed K tile [d][j], padded
    __shared__ __align__(16) float vs[32][32];   // V tile [j][d]
    int tid = threadIdx.x;            // 128
    int qt = blockIdx.x;
    int h = blockIdx.y;
    int b = blockIdx.z;
    int i = qt * 128 + tid;

    const float qscale = 0.17677669529663687f;  // 1/sqrt(32)
    unsigned long long q2[32];  // duplicated {q_d, q_d}
    {
        const float* qp = g_q + (size_t)((b << 10) + i) * CS + h * HD;
#pragma unroll
        for (int d = 0; d < 32; d += 4) {
            float4 v = *(const float4*)(qp + d);
            q2[d + 0] = pack_dup(v.x * qscale);
            q2[d + 1] = pack_dup(v.y * qscale);
            q2[d + 2] = pack_dup(v.z * qscale);
            q2[d + 3] = pack_dup(v.w * qscale);
        }
    }
    unsigned long long ov2[16];
#pragma unroll
    for (int d = 0; d < 16; d++) ov2[d] = 0ULL;
    float m = -1e30f, l = 0.f;

    const float* biasRow = g_bias + ((size_t)h << 20) + ((size_t)i << 10);
    const float* betaRow = beta + ((size_t)((b << 10) + i) << 10);

    int jj0 = tid >> 2;   // 0..31
    int e0 = tid & 3;     // 0..3

    for (int kt = 0; kt < 32; kt++) {
        int j0 = kt * 32;
        __syncthreads();
        {
            const float* kb = g_k + (size_t)((b << 10) + j0 + jj0) * CS + h * HD;
            const float* vb = g_v + (size_t)((b << 10) + j0 + jj0) * CS + h * HD;
            float4 k1 = *(const float4*)(kb + e0 * 4);
            float4 k2 = *(const float4*)(kb + (e0 + 4) * 4);
            kts[e0 * 4 + 0][jj0] = k1.x;
            kts[e0 * 4 + 1][jj0] = k1.y;
            kts[e0 * 4 + 2][jj0] = k1.z;
            kts[e0 * 4 + 3][jj0] = k1.w;
            kts[e0 * 4 + 16][jj0] = k2.x;
            kts[e0 * 4 + 17][jj0] = k2.y;
            kts[e0 * 4 + 18][jj0] = k2.z;
            kts[e0 * 4 + 19][jj0] = k2.w;
            *(float4*)&vs[jj0][e0 * 4] = *(const float4*)(vb + e0 * 4);
            *(float4*)&vs[jj0][(e0 + 4) * 4] = *(const float4*)(vb + (e0 + 4) * 4);
        }
        __syncthreads();

        // scores: pairs along j, init with bias+beta
        unsigned long long sc2[16];
#pragma unroll
        for (int jp = 0; jp < 16; jp++) {
            unsigned long long bbv = *(const unsigned long long*)(biasRow + j0 + 2 * jp);
            unsigned long long btv = *(const unsigned long long*)(betaRow + j0 + 2 * jp);
            sc2[jp] = add2(bbv, btv);
        }
#pragma unroll
        for (int jp = 0; jp < 16; jp += 4) {
#pragma unroll
            for (int d = 0; d < 32; d++) {
                unsigned long long k0v = *(const unsigned long long*)&kts[d][2 * jp + 0];
                unsigned long long k1v = *(const unsigned long long*)&kts[d][2 * jp + 2];
                unsigned long long k2v = *(const unsigned long long*)&kts[d][2 * jp + 4];
                unsigned long long k3v = *(const unsigned long long*)&kts[d][2 * jp + 6];
                FMA2(sc2[jp + 0], q2[d], k0v);
                FMA2(sc2[jp + 1], q2[d], k1v);
                FMA2(sc2[jp + 2], q2[d], k2v);
                FMA2(sc2[jp + 3], q2[d], k3v);
            }
        }
        float sc[32];
        float tm = -1e30f;
#pragma unroll
        for (int jp = 0; jp < 16; jp++) {
            float2 u = unpack2(sc2[jp]);
            sc[2 * jp] = u.x;
            sc[2 * jp + 1] = u.y;
            tm = fmaxf(tm, fmaxf(u.x, u.y));
        }
        float mn = fmaxf(m, tm);
        float f = __expf(m - mn);
        l *= f;
        unsigned long long f2 = pack_dup(f);
#pragma unroll
        for (int d = 0; d < 16; d++) MUL2(ov2[d], f2);
#pragma unroll
        for (int jj = 0; jj < 32; jj++) {
            float pw = __expf(sc[jj] - mn);
            l += pw;
            unsigned long long pw2 = pack_dup(pw);
#pragma unroll
            for (int d = 0; d < 16; d++) {
                unsigned long long vv = *(const unsigned long long*)&vs[jj][2 * d];
                FMA2(ov2[d], pw2, vv);
            }
        }
        m = mn;
    }
    float inv = 1.f / l;
    float* op = g_ao + (size_t)((b << 10) + i) * CS + h * HD;
#pragma unroll
    for (int d = 0; d < 16; d++) {
        float2 u = unpack2(ov2[d]);
        *(float2*)(op + 2 * d) = make_float2(u.x * inv, u.y * inv);
    }
}

// ---------------- launch ----------------
extern "C" void kernel_launch(void* const* d_in, const int* in_sizes, int n_in,
                              void* d_out, int out_size) {
    (void)in_sizes; (void)n_in; (void)out_size;
    const float* bs      = (const float*)d_in[0];
    const float* z       = (const float*)d_in[1];
    const float* t       = (const float*)d_in[2];
    const float* beta    = (const float*)d_in[3];
    const int*   zmask   = (const int*)d_in[4];
    const float* w_adaln = (const float*)d_in[5];
    const float* b_adaln = (const float*)d_in[6];
    const float* ln_z_w  = (const float*)d_in[7];
    const float* ln_z_b  = (const float*)d_in[8];
    const float* w_q     = (const float*)d_in[9];
    const float* w_k     = (const float*)d_in[10];
    const float* w_v     = (const float*)d_in[11];
    const float* w_z     = (const float*)d_in[12];
    const float* rms_q_w = (const float*)d_in[13];
    const float* rms_k_w = (const float*)d_in[14];
    const float* w_o     = (const float*)d_in[15];
    const float* b_o     = (const float*)d_in[16];
    float* out = (float*)d_out;

    float* gq; cudaGetSymbolAddress((void**)&gq, g_q);
    float* gk; cudaGetSymbolAddress((void**)&gk, g_k);
    float* gv; cudaGetSymbolAddress((void**)&gv, g_v);
    float* gbsn; cudaGetSymbolAddress((void**)&gbsn, g_bsn);
    float* gao; cudaGetSymbolAddress((void**)&gao, g_ao);

    setup_wz_kernel<<<1, 128>>>(ln_z_w, ln_z_b, w_z);
    bias_kernel<<<(S_LEN * S_LEN) / 256, 256>>>(z, zmask);
    emb_kernel<<<dim3(18, NB), 128>>>(t, w_adaln, b_adaln);
    bsnorm_kernel<<<NROWS, 256>>>(bs);

    // fused QKV GEMM: 12 x 16 x 3 tiles of 64x128
    gemm_kernel2<<<dim3(CS / 64, NROWS / 128, 3), 128>>>(
        gbsn, w_q, w_k, w_v, gq, gk, gv, nullptr, 0);

    rms_kernel<<<(NROWS * NH + 255) / 256, 256>>>(rms_q_w, 0);
    rms_kernel<<<(NROWS * NH + 255) / 256, 256>>>(rms_k_w, 1);

    attn_kernel<<<dim3(8, NH, NB), 128>>>(beta);

    gemm_kernel2<<<dim3(CS / 64, NROWS / 128, 1), 128>>>(
        gao, w_o, w_o, w_o, out, out, out, b_o, 1);
}

// round 6
// speedup vs baseline: 1.6141x; 1.6141x over previous
#include <cuda_runtime.h>
#include <cstdint>

#define S_LEN 1024
#define CS 768
#define CZ 128
#define NH 24
#define HD 32
#define NB 2
#define NROWS (NB * S_LEN)      // 2048
#define EPS 1e-5f
#define NEG_INF (-1e9f)

// ---------------- scratch (device globals) ----------------
__device__ float g_emb[NB * 3 * CS];
__device__ float g_bsn[NROWS * CS];
__device__ float g_q[NROWS * CS];
__device__ float g_k[NROWS * CS];
__device__ float g_v[NROWS * CS];
__device__ float g_ao[NROWS * CS];
__device__ float g_bias[(size_t)NH * S_LEN * S_LEN];
__device__ float g_wz2[CZ * NH];
__device__ float g_wsum[NH];
__device__ float g_bias0[NH];

// ---------------- setup: fold ln_z into w_z ----------------
__global__ void setup_wz_kernel(const float* __restrict__ lnw,
                                const float* __restrict__ lnb,
                                const float* __restrict__ wz) {
    int tid = threadIdx.x;  // 128
    for (int idx = tid; idx < CZ * NH; idx += 128) {
        int c = idx / NH;
        g_wz2[idx] = lnw[c] * wz[idx];
    }
    __syncthreads();
    if (tid < NH) {
        float s = 0.f, b0 = 0.f;
        for (int c = 0; c < CZ; c++) {
            s += g_wz2[c * NH + tid];
            b0 += lnb[c] * wz[c * NH + tid];
        }
        g_wsum[tid] = s;
        g_bias0[tid] = b0;
    }
}

// ---------------- adaLN embedding, parallel over output columns ----------------
// grid (18, NB) x 128 threads: one output column per thread (2304 cols/batch)
__global__ void emb_kernel(const float* __restrict__ t,
                           const float* __restrict__ w,
                           const float* __restrict__ ba) {
    __shared__ float st[CS];
    int b = blockIdx.y;
    int tid = threadIdx.x;
    int col = blockIdx.x * 128 + tid;
    for (int kk = tid; kk < CS; kk += 128) {
        float x = t[b * CS + kk];
        st[kk] = x / (1.f + __expf(-x));
    }
    __syncthreads();
    float acc = ba[col];
#pragma unroll 8
    for (int k = 0; k < CS; k++)
        acc = fmaf(st[k], w[(size_t)k * (3 * CS) + col], acc);
    g_emb[b * 3 * CS + col] = acc;
}

// ---------------- bs LayerNorm + adaLN modulate ----------------
__global__ void bsnorm_kernel(const float* __restrict__ bs) {
    int r = blockIdx.x;
    int tid = threadIdx.x;  // 256
    int b = r >> 10;
    const float* x = bs + (size_t)r * CS;
    float v[3];
    float s = 0.f, s2 = 0.f;
#pragma unroll
    for (int k = 0; k < 3; k++) {
        v[k] = x[tid + k * 256];
        s += v[k];
        s2 = fmaf(v[k], v[k], s2);
    }
#pragma unroll
    for (int o = 16; o > 0; o >>= 1) {
        s += __shfl_xor_sync(0xffffffffu, s, o);
        s2 += __shfl_xor_sync(0xffffffffu, s2, o);
    }
    __shared__ float rs[8], rs2[8];
    int wid = tid >> 5, lane = tid & 31;
    if (lane == 0) { rs[wid] = s; rs2[wid] = s2; }
    __syncthreads();
    float S = 0.f, S2 = 0.f;
#pragma unroll
    for (int w = 0; w < 8; w++) { S += rs[w]; S2 += rs2[w]; }
    float mu = S * (1.f / CS);
    float var = S2 * (1.f / CS) - mu * mu;
    float rstd = rsqrtf(var + EPS);
    const float* eb = g_emb + b * 3 * CS;
#pragma unroll
    for (int k = 0; k < 3; k++) {
        int c = tid + k * 256;
        g_bsn[(size_t)r * CS + c] = (v[k] - mu) * rstd * (1.f + eb[CS + c]) + eb[c];
    }
}

// ---------------- scalar fp32 GEMM: 128x128 tile, 256 thr, 8x8 micro-tile ----------------
// z selects (W,C); epi=1 applies (x+bo)*gate.
__global__ __launch_bounds__(256, 2) void gemm8_kernel(
    const float* __restrict__ A,
    const float* __restrict__ Wa, const float* __restrict__ Wb, const float* __restrict__ Wc,
    float* __restrict__ Ca, float* __restrict__ Cb, float* __restrict__ Cc,
    const float* __restrict__ bo, int epi) {
    __shared__ float As[2][8][132];   // [k][row]
    __shared__ float Bs[2][8][132];   // [k][col]

    int tid = threadIdx.x;
    int z = blockIdx.z;
    const float* W = (z == 0) ? Wa : (z == 1) ? Wb : Wc;
    float* C = (z == 0) ? Ca : (z == 1) ? Cb : Cc;

    int row0 = blockIdx.y * 128;
    int col0 = blockIdx.x * 128;
    int tx = tid & 15, ty = tid >> 4;
    int rf = ty * 8, cf = tx * 8;

    int aRow = tid >> 1, aq = (tid & 1) * 4;   // A: 128 rows x 8 k
    int bK = tid >> 5, bc = (tid & 31) * 4;    // B: 8 k x 128 cols

    float acc[8][8];
#pragma unroll
    for (int i = 0; i < 8; i++)
#pragma unroll
        for (int j = 0; j < 8; j++) acc[i][j] = 0.f;

    float4 ra = *(const float4*)&A[(size_t)(row0 + aRow) * CS + aq];
    float4 rb = *(const float4*)&W[(size_t)bK * CS + col0 + bc];

    int buf = 0;
    for (int kt = 0; kt < 96; kt++) {
        As[buf][aq + 0][aRow] = ra.x;
        As[buf][aq + 1][aRow] = ra.y;
        As[buf][aq + 2][aRow] = ra.z;
        As[buf][aq + 3][aRow] = ra.w;
        *(float4*)&Bs[buf][bK][bc] = rb;
        __syncthreads();
        if (kt < 95) {
            int k0 = (kt + 1) * 8;
            ra = *(const float4*)&A[(size_t)(row0 + aRow) * CS + k0 + aq];
            rb = *(const float4*)&W[(size_t)(k0 + bK) * CS + col0 + bc];
        }
#pragma unroll
        for (int k = 0; k < 8; k++) {
            float a[8], b[8];
            *(float4*)&a[0] = *(const float4*)&As[buf][k][rf];
            *(float4*)&a[4] = *(const float4*)&As[buf][k][rf + 4];
            *(float4*)&b[0] = *(const float4*)&Bs[buf][k][cf];
            *(float4*)&b[4] = *(const float4*)&Bs[buf][k][cf + 4];
#pragma unroll
            for (int i = 0; i < 8; i++)
#pragma unroll
                for (int j = 0; j < 8; j++) acc[i][j] = fmaf(a[i], b[j], acc[i][j]);
        }
        buf ^= 1;
    }

#pragma unroll
    for (int i = 0; i < 8; i++) {
        int row = row0 + rf + i;
        int col = col0 + cf;
        if (epi) {
            const float* eb = g_emb + (row >> 10) * 3 * CS + 2 * CS + col;
#pragma unroll
            for (int j = 0; j < 8; j++)
                acc[i][j] = (acc[i][j] + bo[col + j]) * eb[j];
        }
        *(float4*)&C[(size_t)row * CS + col] =
            make_float4(acc[i][0], acc[i][1], acc[i][2], acc[i][3]);
        *(float4*)&C[(size_t)row * CS + col + 4] =
            make_float4(acc[i][4], acc[i][5], acc[i][6], acc[i][7]);
    }
}

// ---------------- RMS norm over D=32 groups ----------------
__global__ void rms_kernel(const float* __restrict__ w, int which) {
    int g = blockIdx.x * blockDim.x + threadIdx.x;
    if (g >= NROWS * NH) return;
    float* p = ((which == 0) ? g_q : g_k) + (size_t)g * HD;
    float4 v[8];
    float ss = 0.f;
#pragma unroll
    for (int e = 0; e < 8; e++) {
        v[e] = ((float4*)p)[e];
        ss = fmaf(v[e].x, v[e].x, ss);
        ss = fmaf(v[e].y, v[e].y, ss);
        ss = fmaf(v[e].z, v[e].z, ss);
        ss = fmaf(v[e].w, v[e].w, ss);
    }
    float r = rsqrtf(ss * (1.f / HD) + EPS);
#pragma unroll
    for (int e = 0; e < 8; e++) {
        v[e].x *= r * w[e * 4 + 0];
        v[e].y *= r * w[e * 4 + 1];
        v[e].z *= r * w[e * 4 + 2];
        v[e].w *= r * w[e * 4 + 3];
        ((float4*)p)[e] = v[e];
    }
}

// ---------------- z bias: LN(z) @ wz + mask (f32x2, unchanged from R1 pass) ----------------
__global__ __launch_bounds__(256) void bias_kernel(const float* __restrict__ z,
                                                   const int* __restrict__ zmask) {
    __shared__ float swz[CZ * NH];
    __shared__ float swsum[NH], sbias0[NH];
    int tid = threadIdx.x;
    for (int idx = tid; idx < CZ * NH; idx += 256) swz[idx] = g_wz2[idx];
    if (tid < NH) { swsum[tid] = g_wsum[tid]; sbias0[tid] = g_bias0[tid]; }
    __syncthreads();

    int p = blockIdx.x * 256 + tid;
    int i = p >> 10, j = p & 1023;
    int msk = zmask[p];

    unsigned long long acc[12];
#pragma unroll
    for (int q = 0; q < 12; q++) acc[q] = 0ULL;
    float s = 0.f, s2 = 0.f;

    if (msk) {
        const float4* zp = (const float4*)(z + ((size_t)p << 7));
#pragma unroll 2
        for (int c4 = 0; c4 < 32; c4++) {
            float4 zv = __ldg(&zp[c4]);
            float ze[4] = {zv.x, zv.y, zv.z, zv.w};
#pragma unroll
            for (int e = 0; e < 4; e++) {
                float zc = ze[e];
                s += zc;
                s2 = fmaf(zc, zc, s2);
                unsigned long long zz;
                asm("mov.b64 %0, {%1, %1};" : "=l"(zz) : "r"(__float_as_uint(zc)));
                const unsigned long long* wp =
                    (const unsigned long long*)(swz + (c4 * 4 + e) * NH);
#pragma unroll
                for (int q = 0; q < 12; q++) {
                    asm("fma.rn.f32x2 %0, %1, %2, %0;"
                        : "+l"(acc[q]) : "l"(zz), "l"(wp[q]));
                }
            }
        }
    }
    float mu = s * (1.f / CZ);
    float var = s2 * (1.f / CZ) - mu * mu;
    float rinv = rsqrtf(var + EPS);
    float* ob = g_bias + ((size_t)i << 10) + j;
#pragma unroll
    for (int q = 0; q < 12; q++) {
        unsigned lo, hi;
        asm("mov.b64 {%0, %1}, %2;" : "=r"(lo), "=r"(hi) : "l"(acc[q]));
        int h0 = 2 * q, h1 = 2 * q + 1;
        float v0 = rinv * (__uint_as_float(lo) - mu * swsum[h0]) + sbias0[h0];
        float v1 = rinv * (__uint_as_float(hi) - mu * swsum[h1]) + sbias0[h1];
        ob[(size_t)h0 << 20] = msk ? v0 : NEG_INF;
        ob[(size_t)h1 << 20] = msk ? v1 : NEG_INF;
    }
}

// ---------------- flash attention, scalar fp32 (R1 known-good) ----------------
__global__ __launch_bounds__(128, 3) void attn_kernel(const float* __restrict__ beta) {
    __shared__ float ks[32][32];
    __shared__ float vs[32][32];
    int tid = threadIdx.x;            // 128
    int qt = blockIdx.x;
    int h = blockIdx.y;
    int b = blockIdx.z;
    int i = qt * 128 + tid;

    const float qscale = 0.17677669529663687f;  // 1/sqrt(32)
    float4 qv[8];
    const float4* qp = (const float4*)(g_q + (size_t)((b << 10) + i) * CS + h * HD);
#pragma unroll
    for (int e = 0; e < 8; e++) {
        qv[e] = qp[e];
        qv[e].x *= qscale; qv[e].y *= qscale; qv[e].z *= qscale; qv[e].w *= qscale;
    }
    float4 ov[8];
#pragma unroll
    for (int e = 0; e < 8; e++) ov[e] = make_float4(0.f, 0.f, 0.f, 0.f);
    float m = -1e30f, l = 0.f;

    const float* biasRow = g_bias + ((size_t)h << 20) + ((size_t)i << 10);
    const float* betaRow = beta + ((size_t)((b << 10) + i) << 10);

    int jj0 = tid >> 2;
    int e0 = tid & 3;

    for (int kt = 0; kt < 32; kt++) {
        int j0 = kt * 32;
        __syncthreads();
        {
            const float* kb = g_k + (size_t)((b << 10) + j0 + jj0) * CS + h * HD;
            const float* vb = g_v + (size_t)((b << 10) + j0 + jj0) * CS + h * HD;
            *(float4*)&ks[jj0][e0 * 4] = *(const float4*)(kb + e0 * 4);
            *(float4*)&ks[jj0][(e0 + 4) * 4] = *(const float4*)(kb + (e0 + 4) * 4);
            *(float4*)&vs[jj0][e0 * 4] = *(const float4*)(vb + e0 * 4);
            *(float4*)&vs[jj0][(e0 + 4) * 4] = *(const float4*)(vb + (e0 + 4) * 4);
        }
        __syncthreads();

        float sc[32];
#pragma unroll
        for (int e = 0; e < 8; e++) {
            float4 bb = *(const float4*)(biasRow + j0 + e * 4);
            float4 bt = *(const float4*)(betaRow + j0 + e * 4);
            sc[e * 4 + 0] = bb.x + bt.x;
            sc[e * 4 + 1] = bb.y + bt.y;
            sc[e * 4 + 2] = bb.z + bt.z;
            sc[e * 4 + 3] = bb.w + bt.w;
        }
#pragma unroll
        for (int jj = 0; jj < 32; jj++) {
            float a0 = 0.f, a1 = 0.f, a2 = 0.f, a3 = 0.f;
#pragma unroll
            for (int e = 0; e < 8; e++) {
                float4 kv = *(const float4*)&ks[jj][e * 4];
                a0 = fmaf(qv[e].x, kv.x, a0);
                a1 = fmaf(qv[e].y, kv.y, a1);
                a2 = fmaf(qv[e].z, kv.z, a2);
                a3 = fmaf(qv[e].w, kv.w, a3);
            }
            sc[jj] += (a0 + a1) + (a2 + a3);
        }
        float tm = sc[0];
#pragma unroll
        for (int jj = 1; jj < 32; jj++) tm = fmaxf(tm, sc[jj]);
        float mn = fmaxf(m, tm);
        float f = __expf(m - mn);
        l *= f;
#pragma unroll
        for (int e = 0; e < 8; e++) {
            ov[e].x *= f; ov[e].y *= f; ov[e].z *= f; ov[e].w *= f;
        }
#pragma unroll
        for (int jj = 0; jj < 32; jj++) {
            float pw = __expf(sc[jj] - mn);
            l += pw;
#pragma unroll
            for (int e = 0; e < 8; e++) {
                float4 vv = *(const float4*)&vs[jj][e * 4];
                ov[e].x = fmaf(pw, vv.x, ov[e].x);
                ov[e].y = fmaf(pw, vv.y, ov[e].y);
                ov[e].z = fmaf(pw, vv.z, ov[e].z);
                ov[e].w = fmaf(pw, vv.w, ov[e].w);
            }
        }
        m = mn;
    }
    float inv = 1.f / l;
    float4* op = (float4*)(g_ao + (size_t)((b << 10) + i) * CS + h * HD);
#pragma unroll
    for (int e = 0; e < 8; e++) {
        ov[e].x *= inv; ov[e].y *= inv; ov[e].z *= inv; ov[e].w *= inv;
        op[e] = ov[e];
    }
}

// ---------------- launch ----------------
extern "C" void kernel_launch(void* const* d_in, const int* in_sizes, int n_in,
                              void* d_out, int out_size) {
    (void)in_sizes; (void)n_in; (void)out_size;
    const float* bs      = (const float*)d_in[0];
    const float* z       = (const float*)d_in[1];
    const float* t       = (const float*)d_in[2];
    const float* beta    = (const float*)d_in[3];
    const int*   zmask   = (const int*)d_in[4];
    const float* w_adaln = (const float*)d_in[5];
    const float* b_adaln = (const float*)d_in[6];
    const float* ln_z_w  = (const float*)d_in[7];
    const float* ln_z_b  = (const float*)d_in[8];
    const float* w_q     = (const float*)d_in[9];
    const float* w_k     = (const float*)d_in[10];
    const float* w_v     = (const float*)d_in[11];
    const float* w_z     = (const float*)d_in[12];
    const float* rms_q_w = (const float*)d_in[13];
    const float* rms_k_w = (const float*)d_in[14];
    const float* w_o     = (const float*)d_in[15];
    const float* b_o     = (const float*)d_in[16];
    float* out = (float*)d_out;

    float* gq; cudaGetSymbolAddress((void**)&gq, g_q);
    float* gk; cudaGetSymbolAddress((void**)&gk, g_k);
    float* gv; cudaGetSymbolAddress((void**)&gv, g_v);
    float* gbsn; cudaGetSymbolAddress((void**)&gbsn, g_bsn);
    float* gao; cudaGetSymbolAddress((void**)&gao, g_ao);

    setup_wz_kernel<<<1, 128>>>(ln_z_w, ln_z_b, w_z);
    bias_kernel<<<(S_LEN * S_LEN) / 256, 256>>>(z, zmask);
    emb_kernel<<<dim3(18, NB), 128>>>(t, w_adaln, b_adaln);
    bsnorm_kernel<<<NROWS, 256>>>(bs);

    // fused QKV GEMM: 6 x 16 x 3 blocks of 128x128
    gemm8_kernel<<<dim3(CS / 128, NROWS / 128, 3), 256>>>(
        gbsn, w_q, w_k, w_v, gq, gk, gv, nullptr, 0);

    rms_kernel<<<(NROWS * NH + 255) / 256, 256>>>(rms_q_w, 0);
    rms_kernel<<<(NROWS * NH + 255) / 256, 256>>>(rms_k_w, 1);

    attn_kernel<<<dim3(8, NH, NB), 128>>>(beta);

    gemm8_kernel<<<dim3(CS / 128, NROWS / 128, 1), 256>>>(
        gao, w_o, w_o, w_o, out, out, out, b_o, 1);
}